// round 14
// baseline (speedup 1.0000x reference)
#include <cuda_runtime.h>

#define NG 1024
#define NFEAT 128
#define NQUAD 32          // 128 floats = 32 float4 per row
#define RG 8              // row-groups per block in the pooling kernel
#define SPLIT 6           // blocks per graph

// per-graph node counts (written by s==0 pool block, read by finalize)
__device__ int g_cnt[NG];
// partial sums: [NG][SPLIT][NQUAD] float4  (3 MB)
__device__ float4 g_partial[NG * SPLIT * NQUAD];

// ---------------------------------------------------------------------------
// Warp-cooperative lower_bound on sorted int array: 32 probes per round,
// 33-ary narrowing -> 4 rounds for n = 1e6. All 32 lanes participate.
// Returns smallest i in [0, n] with batch[i] >= target.
// ---------------------------------------------------------------------------
__device__ __forceinline__ int warp_lower_bound(const int* __restrict__ batch,
                                                int n, int target, unsigned lane) {
    int lo = 0, hi = n;                      // lower_bound is in [lo, hi]
    while (hi - lo > 32) {
        int len = hi - lo;
        int pos = lo + (int)(((long long)(lane + 1) * len) / 33);   // in (lo, hi)
        int v = __ldg(&batch[pos]);
        unsigned bal = __ballot_sync(0xFFFFFFFFu, v < target);
        int c = __popc(bal);                 // sorted -> contiguous prefix of trues
        int nlo = lo, nhi = hi;
        if (c > 0)  nlo = lo + (int)(((long long)c * len) / 33) + 1;
        if (c < 32) nhi = lo + (int)(((long long)(c + 1) * len) / 33) + 1;
        lo = nlo; hi = nhi;
    }
    int pos = lo + (int)lane;
    int v = (pos < hi) ? __ldg(&batch[pos]) : 0;
    unsigned bal = __ballot_sync(0xFFFFFFFFu, (pos < hi) && (v < target));
    return lo + __popc(bal);
}

// ---------------------------------------------------------------------------
// K1: partial pooling with self-service bounds. SPLIT blocks per graph.
// Warp 0 finds start(g), warp 1 finds start(g+1) (parallel, ~4 rounds each,
// upper probe levels L2-broadcast-hot across blocks). Then the usual
// deterministic chunk accumulation + fixed tree reduce into g_partial,
// plus fused attention stores.
// ---------------------------------------------------------------------------
__global__ __launch_bounds__(256) void pool_partial_kernel(const float* __restrict__ x,
                                                           const int* __restrict__ batch,
                                                           int ntot,
                                                           float* __restrict__ attn) {
    int bid  = blockIdx.x;
    int g    = bid / SPLIT;
    int s    = bid - g * SPLIT;
    int tid  = threadIdx.x;
    int quad = tid & (NQUAD - 1);
    int rgrp = tid >> 5;
    unsigned lane = tid & 31;

    __shared__ int sb[2];
    if (rgrp == 0) {
        int r = warp_lower_bound(batch, ntot, g, lane);
        if (lane == 0) sb[0] = r;
    } else if (rgrp == 1) {
        int r = warp_lower_bound(batch, ntot, g + 1, lane);
        if (lane == 0) sb[1] = r;
    }
    __syncthreads();

    int start = sb[0];
    int n     = sb[1] - start;
    float inv = 1.0f / (float)(n > 1 ? n : 1);

    if (s == 0 && tid == 0) g_cnt[g] = n;    // for finalize

    int chunk = (n + SPLIT - 1) / SPLIT;
    int r0 = s * chunk;
    int r1 = r0 + chunk; if (r1 > n) r1 = n;
    if (r0 > n) r0 = n;

    const float4* __restrict__ x4 = (const float4*)x;

    float4 acc = make_float4(0.f, 0.f, 0.f, 0.f);

    // Unrolled-by-4 main loop over rows [r0, r1): 4 outstanding 16B loads.
    int r = r0 + rgrp;
    int nmain = r1 - 3 * RG;
    for (; r < nmain; r += 4 * RG) {
        float4 v0 = x4[(size_t)(start + r         ) * NQUAD + quad];
        float4 v1 = x4[(size_t)(start + r + 1 * RG) * NQUAD + quad];
        float4 v2 = x4[(size_t)(start + r + 2 * RG) * NQUAD + quad];
        float4 v3 = x4[(size_t)(start + r + 3 * RG) * NQUAD + quad];
        acc.x += v0.x; acc.y += v0.y; acc.z += v0.z; acc.w += v0.w;
        acc.x += v1.x; acc.y += v1.y; acc.z += v1.z; acc.w += v1.w;
        acc.x += v2.x; acc.y += v2.y; acc.z += v2.z; acc.w += v2.w;
        acc.x += v3.x; acc.y += v3.y; acc.z += v3.z; acc.w += v3.w;
    }
    for (; r < r1; r += RG) {
        float4 v = x4[(size_t)(start + r) * NQUAD + quad];
        acc.x += v.x; acc.y += v.y; acc.z += v.z; acc.w += v.w;
    }

    // fused attention output for this chunk (coalesced fire-and-forget)
    for (int i = r0 + tid; i < r1; i += 256)
        attn[start + i] = inv;

    __shared__ float4 smem[RG * NQUAD];
    smem[rgrp * NQUAD + quad] = acc;
    __syncthreads();

    // tree reduce over row-groups: 8 -> 4 -> 2 -> 1
    #pragma unroll
    for (int half = RG / 2; half >= 1; half >>= 1) {
        if (rgrp < half) {
            float4 a = smem[rgrp * NQUAD + quad];
            float4 b = smem[(rgrp + half) * NQUAD + quad];
            a.x += b.x; a.y += b.y; a.z += b.z; a.w += b.w;
            smem[rgrp * NQUAD + quad] = a;
        }
        __syncthreads();
    }

    if (rgrp == 0)
        g_partial[(size_t)(g * SPLIT + s) * NQUAD + quad] = smem[quad];
}

// ---------------------------------------------------------------------------
// K2: finalize. One thread per (graph, quad): sum the SPLIT partials in fixed
// order, scale by inv, write pooled. 3 MB read (L2-warm), 0.5 MB write.
// ---------------------------------------------------------------------------
__global__ __launch_bounds__(256) void finalize_kernel(float* __restrict__ pooled) {
    int idx = blockIdx.x * blockDim.x + threadIdx.x;   // over NG*NQUAD
    if (idx >= NG * NQUAD) return;
    int g    = idx >> 5;
    int quad = idx & (NQUAD - 1);

    int n = g_cnt[g];
    float inv = 1.0f / (float)(n > 1 ? n : 1);

    const float4* p = &g_partial[(size_t)g * SPLIT * NQUAD + quad];
    float4 a = p[0];
    #pragma unroll
    for (int s = 1; s < SPLIT; s++) {
        float4 b = p[s * NQUAD];
        a.x += b.x; a.y += b.y; a.z += b.z; a.w += b.w;
    }
    a.x *= inv; a.y *= inv; a.z *= inv; a.w *= inv;
    ((float4*)pooled)[idx] = a;
}

// ---------------------------------------------------------------------------
extern "C" void kernel_launch(void* const* d_in, const int* in_sizes, int n_in,
                              void* d_out, int out_size) {
    const float* x     = (const float*)d_in[0];
    // d_in[1] = edge_index (unused by the reference)
    const int*   batch = (const int*)d_in[2];
    int n = in_sizes[2];               // number of nodes (1,000,000)

    float* pooled = (float*)d_out;                 // [NG, NFEAT]
    float* attn   = (float*)d_out + NG * NFEAT;    // [n]

    pool_partial_kernel<<<NG * SPLIT, 256>>>(x, batch, n, attn);
    finalize_kernel<<<(NG * NQUAD + 255) / 256, 256>>>(pooled);
}

// round 15
// speedup vs baseline: 1.0490x; 1.0490x over previous
#include <cuda_runtime.h>

#define NG 1024
#define NFEAT 128
#define NQUAD 32          // 128 floats = 32 float4 per row
#define RG 8              // row-groups per block in the pooling kernel
#define SPLIT 6           // blocks per graph

// g_start[g] = index of first node of graph g; g_start[NG] = n.
__device__ int g_start[NG + 1];
// partial sums: [NG][SPLIT][NFEAT] floats  (3 MB), stored as float4 by pool
__device__ float4 g_partial[NG * SPLIT * NQUAD];

// ---------------------------------------------------------------------------
// K1: boundary detection on sorted batch. int4 loads, 4 nodes per thread.
// ---------------------------------------------------------------------------
__global__ __launch_bounds__(256) void bounds_kernel(const int* __restrict__ batch, int n) {
    int q = blockIdx.x * blockDim.x + threadIdx.x;
    int nq = n >> 2;
    if (q < nq) {
        int4 b = ((const int4*)batch)[q];
        int j = q << 2;
        int prev = (j == 0) ? -1 : batch[j - 1];

        if (b.x > prev) for (int g = prev + 1; g <= b.x; g++) g_start[g] = j;
        if (b.y > b.x)  for (int g = b.x  + 1; g <= b.y; g++) g_start[g] = j + 1;
        if (b.z > b.y)  for (int g = b.y  + 1; g <= b.z; g++) g_start[g] = j + 2;
        if (b.w > b.z)  for (int g = b.z  + 1; g <= b.w; g++) g_start[g] = j + 3;

        if (j + 4 >= (nq << 2)) {
            // last vector thread: handle scalar tail + close remaining graphs
            int last = b.w;
            for (int i = nq << 2; i < n; i++) {
                int c = batch[i];
                for (int g = last + 1; g <= c; g++) g_start[g] = i;
                last = c;
            }
            for (int g = last + 1; g <= NG; g++) g_start[g] = n;
        }
    }
}

// ---------------------------------------------------------------------------
// K2: partial pooling. SPLIT blocks per graph, each sums a contiguous chunk
// of the graph's rows (deterministic per-thread order + fixed tree reduce)
// into g_partial. Also writes the fused attention scores for its chunk.
// ---------------------------------------------------------------------------
__global__ __launch_bounds__(256) void pool_partial_kernel(const float* __restrict__ x,
                                                           float* __restrict__ attn) {
    int bid  = blockIdx.x;
    int g    = bid / SPLIT;
    int s    = bid - g * SPLIT;
    int tid  = threadIdx.x;
    int quad = tid & (NQUAD - 1);
    int rgrp = tid >> 5;

    int start = g_start[g];
    int n     = g_start[g + 1] - start;
    float inv = 1.0f / (float)(n > 1 ? n : 1);

    int chunk = (n + SPLIT - 1) / SPLIT;
    int r0 = s * chunk;
    int r1 = r0 + chunk; if (r1 > n) r1 = n;
    if (r0 > n) r0 = n;

    const float4* __restrict__ x4 = (const float4*)x;

    float4 acc = make_float4(0.f, 0.f, 0.f, 0.f);

    // Unrolled-by-4 main loop over rows [r0, r1): 4 outstanding 16B loads.
    int r = r0 + rgrp;
    int nmain = r1 - 3 * RG;
    for (; r < nmain; r += 4 * RG) {
        float4 v0 = x4[(size_t)(start + r         ) * NQUAD + quad];
        float4 v1 = x4[(size_t)(start + r + 1 * RG) * NQUAD + quad];
        float4 v2 = x4[(size_t)(start + r + 2 * RG) * NQUAD + quad];
        float4 v3 = x4[(size_t)(start + r + 3 * RG) * NQUAD + quad];
        acc.x += v0.x; acc.y += v0.y; acc.z += v0.z; acc.w += v0.w;
        acc.x += v1.x; acc.y += v1.y; acc.z += v1.z; acc.w += v1.w;
        acc.x += v2.x; acc.y += v2.y; acc.z += v2.z; acc.w += v2.w;
        acc.x += v3.x; acc.y += v3.y; acc.z += v3.z; acc.w += v3.w;
    }
    for (; r < r1; r += RG) {
        float4 v = x4[(size_t)(start + r) * NQUAD + quad];
        acc.x += v.x; acc.y += v.y; acc.z += v.z; acc.w += v.w;
    }

    // fused attention output for this chunk (coalesced fire-and-forget)
    for (int i = r0 + tid; i < r1; i += 256)
        attn[start + i] = inv;

    __shared__ float4 smem[RG * NQUAD];
    smem[rgrp * NQUAD + quad] = acc;
    __syncthreads();

    // tree reduce over row-groups: 8 -> 4 -> 2 -> 1
    #pragma unroll
    for (int half = RG / 2; half >= 1; half >>= 1) {
        if (rgrp < half) {
            float4 a = smem[rgrp * NQUAD + quad];
            float4 b = smem[(rgrp + half) * NQUAD + quad];
            a.x += b.x; a.y += b.y; a.z += b.z; a.w += b.w;
            smem[rgrp * NQUAD + quad] = a;
        }
        __syncthreads();
    }

    if (rgrp == 0)
        g_partial[(size_t)(g * SPLIT + s) * NQUAD + quad] = smem[quad];
}

// ---------------------------------------------------------------------------
// K3: finalize, scalar-float granularity for 4x parallelism vs the float4
// version (512 blocks instead of 128 -> latency hidden). One thread per
// (graph, feature): sums SPLIT partials in fixed order, scales, writes.
// Consecutive threads read consecutive floats within each s-slice -> fully
// coalesced. Deterministic.
// ---------------------------------------------------------------------------
__global__ __launch_bounds__(256) void finalize_kernel(float* __restrict__ pooled) {
    int idx = blockIdx.x * blockDim.x + threadIdx.x;   // over NG*NFEAT
    if (idx >= NG * NFEAT) return;
    int g = idx >> 7;                 // / NFEAT
    int f = idx & (NFEAT - 1);

    int n = g_start[g + 1] - g_start[g];
    float inv = 1.0f / (float)(n > 1 ? n : 1);

    const float* p = (const float*)&g_partial[(size_t)g * SPLIT * NQUAD];
    float a = p[f];
    #pragma unroll
    for (int s = 1; s < SPLIT; s++)
        a += p[s * NFEAT + f];
    pooled[idx] = a * inv;
}

// ---------------------------------------------------------------------------
extern "C" void kernel_launch(void* const* d_in, const int* in_sizes, int n_in,
                              void* d_out, int out_size) {
    const float* x     = (const float*)d_in[0];
    // d_in[1] = edge_index (unused by the reference)
    const int*   batch = (const int*)d_in[2];
    int n = in_sizes[2];               // number of nodes (1,000,000)

    float* pooled = (float*)d_out;                 // [NG, NFEAT]
    float* attn   = (float*)d_out + NG * NFEAT;    // [n]

    int nq = n >> 2;
    bounds_kernel<<<(nq + 255) / 256, 256>>>(batch, n);
    pool_partial_kernel<<<NG * SPLIT, 256>>>(x, attn);
    finalize_kernel<<<(NG * NFEAT + 255) / 256, 256>>>(pooled);
}

// round 17
// speedup vs baseline: 1.0577x; 1.0082x over previous
#include <cuda_runtime.h>

#define NG 1024
#define NFEAT 128
#define NQUAD 32          // 128 floats = 32 float4 per row
#define RG 8              // row-groups per block in the pooling kernel
#define SPLIT 6           // blocks per graph

// g_start[g] = index of first node of graph g; g_start[NG] = n.
__device__ int g_start[NG + 1];
// partial sums: [NG][SPLIT][NFEAT] floats  (3 MB), stored as float4 by pool
__device__ float4 g_partial[NG * SPLIT * NQUAD];

// ---------------------------------------------------------------------------
// K1: boundary detection on sorted batch. int4 loads, 4 nodes per thread.
// (primary of the PDL pair; completion implicitly triggers at kernel end)
// ---------------------------------------------------------------------------
__global__ __launch_bounds__(256) void bounds_kernel(const int* __restrict__ batch, int n) {
    int q = blockIdx.x * blockDim.x + threadIdx.x;
    int nq = n >> 2;
    if (q < nq) {
        int4 b = ((const int4*)batch)[q];
        int j = q << 2;
        int prev = (j == 0) ? -1 : batch[j - 1];

        if (b.x > prev) for (int g = prev + 1; g <= b.x; g++) g_start[g] = j;
        if (b.y > b.x)  for (int g = b.x  + 1; g <= b.y; g++) g_start[g] = j + 1;
        if (b.z > b.y)  for (int g = b.y  + 1; g <= b.z; g++) g_start[g] = j + 2;
        if (b.w > b.z)  for (int g = b.z  + 1; g <= b.w; g++) g_start[g] = j + 3;

        if (j + 4 >= (nq << 2)) {
            // last vector thread: handle scalar tail + close remaining graphs
            int last = b.w;
            for (int i = nq << 2; i < n; i++) {
                int c = batch[i];
                for (int g = last + 1; g <= c; g++) g_start[g] = i;
                last = c;
            }
            for (int g = last + 1; g <= NG; g++) g_start[g] = n;
        }
    }
}

// ---------------------------------------------------------------------------
// K2: partial pooling. SPLIT blocks per graph. Launched with PDL: the grid
// goes resident while bounds_kernel still runs; cudaGridDependencySynchronize
// gates the first g_start read. Deterministic accumulation + fixed tree
// reduce into g_partial, plus fused attention stores.
// ---------------------------------------------------------------------------
__global__ __launch_bounds__(256) void pool_partial_kernel(const float* __restrict__ x,
                                                           float* __restrict__ attn) {
    int bid  = blockIdx.x;
    int g    = bid / SPLIT;
    int s    = bid - g * SPLIT;
    int tid  = threadIdx.x;
    int quad = tid & (NQUAD - 1);
    int rgrp = tid >> 5;

    cudaGridDependencySynchronize();   // wait for bounds_kernel's g_start

    int start = g_start[g];
    int n     = g_start[g + 1] - start;
    float inv = 1.0f / (float)(n > 1 ? n : 1);

    int chunk = (n + SPLIT - 1) / SPLIT;
    int r0 = s * chunk;
    int r1 = r0 + chunk; if (r1 > n) r1 = n;
    if (r0 > n) r0 = n;

    const float4* __restrict__ x4 = (const float4*)x;

    float4 acc = make_float4(0.f, 0.f, 0.f, 0.f);

    // Unrolled-by-4 main loop over rows [r0, r1): 4 outstanding 16B loads.
    int r = r0 + rgrp;
    int nmain = r1 - 3 * RG;
    for (; r < nmain; r += 4 * RG) {
        float4 v0 = x4[(size_t)(start + r         ) * NQUAD + quad];
        float4 v1 = x4[(size_t)(start + r + 1 * RG) * NQUAD + quad];
        float4 v2 = x4[(size_t)(start + r + 2 * RG) * NQUAD + quad];
        float4 v3 = x4[(size_t)(start + r + 3 * RG) * NQUAD + quad];
        acc.x += v0.x; acc.y += v0.y; acc.z += v0.z; acc.w += v0.w;
        acc.x += v1.x; acc.y += v1.y; acc.z += v1.z; acc.w += v1.w;
        acc.x += v2.x; acc.y += v2.y; acc.z += v2.z; acc.w += v2.w;
        acc.x += v3.x; acc.y += v3.y; acc.z += v3.z; acc.w += v3.w;
    }
    for (; r < r1; r += RG) {
        float4 v = x4[(size_t)(start + r) * NQUAD + quad];
        acc.x += v.x; acc.y += v.y; acc.z += v.z; acc.w += v.w;
    }

    // fused attention output for this chunk (coalesced fire-and-forget)
    for (int i = r0 + tid; i < r1; i += 256)
        attn[start + i] = inv;

    __shared__ float4 smem[RG * NQUAD];
    smem[rgrp * NQUAD + quad] = acc;
    __syncthreads();

    // tree reduce over row-groups: 8 -> 4 -> 2 -> 1
    #pragma unroll
    for (int half = RG / 2; half >= 1; half >>= 1) {
        if (rgrp < half) {
            float4 a = smem[rgrp * NQUAD + quad];
            float4 b = smem[(rgrp + half) * NQUAD + quad];
            a.x += b.x; a.y += b.y; a.z += b.z; a.w += b.w;
            smem[rgrp * NQUAD + quad] = a;
        }
        __syncthreads();
    }

    if (rgrp == 0)
        g_partial[(size_t)(g * SPLIT + s) * NQUAD + quad] = smem[quad];
}

// ---------------------------------------------------------------------------
// K3: finalize, scalar-float granularity (512 blocks). Also PDL-launched so
// its launch latency hides behind pool's tail wave. One thread per
// (graph, feature): sums SPLIT partials in fixed order, scales, writes.
// ---------------------------------------------------------------------------
__global__ __launch_bounds__(256) void finalize_kernel(float* __restrict__ pooled) {
    cudaGridDependencySynchronize();   // wait for pool's g_partial

    int idx = blockIdx.x * blockDim.x + threadIdx.x;   // over NG*NFEAT
    if (idx >= NG * NFEAT) return;
    int g = idx >> 7;                 // / NFEAT
    int f = idx & (NFEAT - 1);

    int n = g_start[g + 1] - g_start[g];
    float inv = 1.0f / (float)(n > 1 ? n : 1);

    const float* p = (const float*)&g_partial[(size_t)g * SPLIT * NQUAD];
    float a = p[f];
    #pragma unroll
    for (int s = 1; s < SPLIT; s++)
        a += p[s * NFEAT + f];
    pooled[idx] = a * inv;
}

// ---------------------------------------------------------------------------
extern "C" void kernel_launch(void* const* d_in, const int* in_sizes, int n_in,
                              void* d_out, int out_size) {
    const float* x     = (const float*)d_in[0];
    // d_in[1] = edge_index (unused by the reference)
    const int*   batch = (const int*)d_in[2];
    int n = in_sizes[2];               // number of nodes (1,000,000)

    float* pooled = (float*)d_out;                 // [NG, NFEAT]
    float* attn   = (float*)d_out + NG * NFEAT;    // [n]

    int nq = n >> 2;
    bounds_kernel<<<(nq + 255) / 256, 256>>>(batch, n);

    // pool: PDL against bounds
    {
        cudaLaunchConfig_t cfg = {};
        cfg.gridDim  = dim3(NG * SPLIT, 1, 1);
        cfg.blockDim = dim3(256, 1, 1);
        cudaLaunchAttribute attr[1];
        attr[0].id = cudaLaunchAttributeProgrammaticStreamSerialization;
        attr[0].val.programmaticStreamSerializationAllowed = 1;
        cfg.attrs = attr;
        cfg.numAttrs = 1;
        cudaLaunchKernelEx(&cfg, pool_partial_kernel, x, attn);
    }

    // finalize: PDL against pool
    {
        cudaLaunchConfig_t cfg = {};
        cfg.gridDim  = dim3((NG * NFEAT + 255) / 256, 1, 1);
        cfg.blockDim = dim3(256, 1, 1);
        cudaLaunchAttribute attr[1];
        attr[0].id = cudaLaunchAttributeProgrammaticStreamSerialization;
        attr[0].val.programmaticStreamSerializationAllowed = 1;
        cfg.attrs = attr;
        cfg.numAttrs = 1;
        cudaLaunchKernelEx(&cfg, finalize_kernel, pooled);
    }
}